// round 7
// baseline (speedup 1.0000x reference)
#include <cuda_runtime.h>
#include <float.h>

#define BB 64
#define LL 8192
#define DD 64
#define NBLK 8          // blocks per batch (both kernels) -> grid (8, 64) = 512
#define CPB 4           // chunks/tiles per block
#define CH  256         // rows per chunk

// Scratch (device mallocs forbidden)
__device__ float g_partial_acc[BB * NBLK * DD];
__device__ float g_partial_m[BB * NBLK];
__device__ float g_partial_s[BB * NBLK];

// ---------------------------------------------------------------------------
// Collect: per (block, batch) loop over 4 chunks of 256 rows with ONLINE
// softmax. Phases pipeline across chunk iterations: P3 v-loads of chunk i
// overlap P1 kc-loads of chunk i+1 (no dependency through the barriers).
// ---------------------------------------------------------------------------
__global__ void __launch_bounds__(256)
collect_kernel(const float* __restrict__ q,
               const float* __restrict__ kc,
               const float* __restrict__ v,
               const float* __restrict__ tc,
               float* __restrict__ out_logit)
{
    __shared__ float  psum[CH * 17];   // [row][seg], stride-17: conflict-free
    __shared__ float  w_sh[CH];
    __shared__ float  red[16];
    __shared__ float4 q4_sh[16];

    const int t   = threadIdx.x;
    const int blk = blockIdx.x;
    const int b   = blockIdx.y;

    if (t < 16) q4_sh[t] = ((const float4*)(q + b * DD))[t];
    __syncthreads();

    const float inv_tc = 1.0f / *tc;
    const int seg  = t & 15;
    const int rsub = t >> 4;
    const int lane = t & 31;
    const int wid  = t >> 5;
    const float4 qv = q4_sh[seg];

    // phase-3 role: thread owns float2 dim d2, row-group g (8 groups)
    const int d2 = t & 31;
    const int g  = t >> 5;

    float2 acc = make_float2(0.f, 0.f);
    float m_run = -FLT_MAX, s_run = 0.f;

    const float4* kc4 = (const float4*)(kc + (size_t)b * LL * DD);
    const float2* v2  = (const float2*)(v  + (size_t)b * LL * DD);

    for (int ci = 0; ci < CPB; ci++) {
        const int row0 = (blk * CPB + ci) * CH;

        // ---- P1: 16 independent coalesced kc loads -> psum ----
        #pragma unroll
        for (int i = 0; i < 16; i++) {
            const int row = i * 16 + rsub;
            float4 kv = kc4[(size_t)(row0 + row) * 16 + seg];
            psum[row * 17 + seg] =
                kv.x * qv.x + kv.y * qv.y + kv.z * qv.z + kv.w * qv.w;
        }
        __syncthreads();

        // ---- P2: logit, chunk max/sum (cheap warp reductions) ----
        float s = 0.f;
        #pragma unroll
        for (int j = 0; j < 16; j++) s += psum[t * 17 + j];
        const float lg = s * inv_tc;
        out_logit[(size_t)b * LL + row0 + t] = lg;

        float wm = lg;
        wm = fmaxf(wm, __shfl_xor_sync(0xffffffffu, wm, 16));
        wm = fmaxf(wm, __shfl_xor_sync(0xffffffffu, wm, 8));
        wm = fmaxf(wm, __shfl_xor_sync(0xffffffffu, wm, 4));
        wm = fmaxf(wm, __shfl_xor_sync(0xffffffffu, wm, 2));
        wm = fmaxf(wm, __shfl_xor_sync(0xffffffffu, wm, 1));
        if (lane == 0) red[wid] = wm;
        __syncthreads();
        float m_c = red[0];
        #pragma unroll
        for (int i = 1; i < 8; i++) m_c = fmaxf(m_c, red[i]);

        const float w = __expf(lg - m_c);
        w_sh[t] = w;
        float ws = w;
        ws += __shfl_xor_sync(0xffffffffu, ws, 16);
        ws += __shfl_xor_sync(0xffffffffu, ws, 8);
        ws += __shfl_xor_sync(0xffffffffu, ws, 4);
        ws += __shfl_xor_sync(0xffffffffu, ws, 2);
        ws += __shfl_xor_sync(0xffffffffu, ws, 1);
        if (lane == 0) red[8 + wid] = ws;
        __syncthreads();        // guards w_sh for P3 and psum for next P1
        float s_c = 0.f;
        #pragma unroll
        for (int i = 0; i < 8; i++) s_c += red[8 + i];

        // online rescale (all threads track identical scalars)
        const float m_new  = fmaxf(m_run, m_c);
        const float sc_old = __expf(m_run - m_new);   // 0 on first chunk
        const float sc_c   = __expf(m_c - m_new);
        acc.x *= sc_old; acc.y *= sc_old;
        s_run = s_run * sc_old + s_c * sc_c;
        m_run = m_new;

        // ---- P3: streaming weighted-v accumulate (float2 lanes) ----
        float2 va = make_float2(0.f, 0.f);
        const float2* vb = v2 + (size_t)row0 * 32;
        #pragma unroll 8
        for (int r = g; r < CH; r += 8) {
            float2 vv = vb[(size_t)r * 32 + d2];
            float wr = w_sh[r];
            va.x += wr * vv.x; va.y += wr * vv.y;
        }
        acc.x += sc_c * va.x; acc.y += sc_c * va.y;
    }

    // ---- final cross-group reduction (reuse psum as float2 scratch) ----
    float2* redf2 = (float2*)psum;
    redf2[t] = acc;
    __syncthreads();
    if (t < 32) {
        float2 tot = make_float2(0.f, 0.f);
        #pragma unroll
        for (int i = 0; i < 8; i++) {
            float2 x = redf2[i * 32 + t];
            tot.x += x.x; tot.y += x.y;
        }
        ((float2*)(g_partial_acc + ((size_t)b * NBLK + blk) * DD))[t] = tot;
    }
    if (t == 0) {
        g_partial_m[b * NBLK + blk] = m_run;
        g_partial_s[b * NBLK + blk] = s_run;
    }
}

// ---------------------------------------------------------------------------
// Diffuse (fused combine): per (block, batch) loop over 4 tiles of 256 rows.
// Stores of tile i overlap loads of tile i+1; single-buffered SMEM is safe
// through the two per-tile barriers.
// ---------------------------------------------------------------------------
__global__ void __launch_bounds__(256)
diffuse_kernel(const float* __restrict__ q,
               const float* __restrict__ kd,
               const float* __restrict__ td,
               float* __restrict__ out)
{
    __shared__ float  psum[CH * 17];
    __shared__ float  gate_sh[CH];
    __shared__ float  attn_sh[DD];
    __shared__ float4 q4_sh[16];

    const int b   = blockIdx.y;
    const int t   = threadIdx.x;
    const int blk = blockIdx.x;

    // --- combine partials -> attn_sh (threads 0..63; L2-hot) ---
    if (t < DD) {
        float M = -FLT_MAX;
        #pragma unroll
        for (int i = 0; i < NBLK; i++)
            M = fmaxf(M, g_partial_m[b * NBLK + i]);
        float S = 0.f, num = 0.f;
        #pragma unroll
        for (int i = 0; i < NBLK; i++) {
            float e = __expf(g_partial_m[b * NBLK + i] - M);
            S   += g_partial_s[b * NBLK + i] * e;
            num += g_partial_acc[((size_t)b * NBLK + i) * DD + t] * e;
        }
        attn_sh[t] = num / S;
    }
    if (t < 16) q4_sh[t] = ((const float4*)(q + b * DD))[t];
    __syncthreads();

    const float inv_td = 1.0f / *td;
    const int seg  = t & 15;
    const int rsub = t >> 4;
    const float4 qv = q4_sh[seg];
    const float4 av = ((const float4*)attn_sh)[seg];

    const float4* kd4 = (const float4*)(kd + (size_t)b * LL * DD);
    float4* o4 = (float4*)(out + (size_t)b * LL * DD);

    for (int ci = 0; ci < CPB; ci++) {
        const int row0 = (blk * CPB + ci) * CH;

        // ---- P1: 16 independent coalesced kd loads -> psum ----
        #pragma unroll
        for (int i = 0; i < 16; i++) {
            const int row = i * 16 + rsub;
            float4 kv = kd4[(size_t)(row0 + row) * 16 + seg];
            psum[row * 17 + seg] =
                kv.x * qv.x + kv.y * qv.y + kv.z * qv.z + kv.w * qv.w;
        }
        __syncthreads();        // also guards gate_sh against P3 of prev tile

        // ---- P2: gate ----
        float s = 0.f;
        #pragma unroll
        for (int j = 0; j < 16; j++) s += psum[t * 17 + j];
        gate_sh[t] = 1.0f / (1.0f + __expf(-s * inv_td));
        __syncthreads();        // guards psum against next P1

        // ---- P3: pure streaming store (overlaps next tile's P1) ----
        #pragma unroll
        for (int i = 0; i < 16; i++) {
            const int row = i * 16 + rsub;
            const float gg = gate_sh[row];
            o4[(size_t)(row0 + row) * 16 + seg] =
                make_float4(gg * av.x, gg * av.y, gg * av.z, gg * av.w);
        }
    }
}

// ---------------------------------------------------------------------------
extern "C" void kernel_launch(void* const* d_in, const int* in_sizes, int n_in,
                              void* d_out, int out_size)
{
    const float* q  = (const float*)d_in[0];
    const float* kc = (const float*)d_in[1];
    const float* kd = (const float*)d_in[2];
    const float* v  = (const float*)d_in[3];
    const float* tc = (const float*)d_in[4];
    const float* td = (const float*)d_in[5];

    float* out_main  = (float*)d_out;                         // [B, L, D]
    float* out_logit = (float*)d_out + (size_t)BB * LL * DD;  // [B, L]

    collect_kernel<<<dim3(NBLK, BB), 256>>>(q, kc, v, tc, out_logit);
    diffuse_kernel<<<dim3(NBLK, BB), 256>>>(q, kd, td, out_main);
}

// round 8
// speedup vs baseline: 1.1313x; 1.1313x over previous
#include <cuda_runtime.h>
#include <float.h>

#define BB 64
#define LL 8192
#define DD 64
#define NSPLIT 32
#define CH 256          // rows per block/chunk

// Scratch (device mallocs forbidden)
__device__ float g_partial_acc[BB * NSPLIT * DD];
__device__ float g_partial_m[BB * NSPLIT];
__device__ float g_partial_s[BB * NSPLIT];

// ---------------------------------------------------------------------------
// Collect: one 256-row chunk per block. grid (32, 64), 256 threads.
// Shuffle-based block reductions (3 syncs total), float2 v-accumulate.
// launch_bounds caps regs at ~42 -> 6 blocks/SM (48 warps).
// ---------------------------------------------------------------------------
__global__ void __launch_bounds__(256, 6)
collect_kernel(const float* __restrict__ q,
               const float* __restrict__ kc,
               const float* __restrict__ v,
               const float* __restrict__ tc,
               float* __restrict__ out_logit)
{
    __shared__ float  psum[CH * 17];   // [row][seg], stride-17: conflict-free
    __shared__ float  w_sh[CH];
    __shared__ float  red[16];
    __shared__ float4 q4_sh[16];

    const int t = threadIdx.x;
    const int c = blockIdx.x;
    const int b = blockIdx.y;
    const int row0 = c * CH;

    if (t < 16) q4_sh[t] = ((const float4*)(q + b * DD))[t];
    __syncthreads();

    const float inv_tc = 1.0f / *tc;
    const int seg  = t & 15;
    const int rsub = t >> 4;
    const int lane = t & 31;
    const int wid  = t >> 5;
    const float4 qv = q4_sh[seg];

    // ---- P1: 16 independent coalesced kc loads -> psum ----
    const float4* kc4 = (const float4*)(kc + (size_t)b * LL * DD);
    #pragma unroll
    for (int i = 0; i < 16; i++) {
        const int row = i * 16 + rsub;
        float4 kv = kc4[(size_t)(row0 + row) * 16 + seg];
        psum[row * 17 + seg] =
            kv.x * qv.x + kv.y * qv.y + kv.z * qv.z + kv.w * qv.w;
    }
    __syncthreads();

    // ---- P2: row reduce -> logit (write it); block max/sum via shuffles ----
    float s = 0.f;
    #pragma unroll
    for (int j = 0; j < 16; j++) s += psum[t * 17 + j];
    const float lg = s * inv_tc;
    out_logit[(size_t)b * LL + row0 + t] = lg;

    float wm = lg;
    wm = fmaxf(wm, __shfl_xor_sync(0xffffffffu, wm, 16));
    wm = fmaxf(wm, __shfl_xor_sync(0xffffffffu, wm, 8));
    wm = fmaxf(wm, __shfl_xor_sync(0xffffffffu, wm, 4));
    wm = fmaxf(wm, __shfl_xor_sync(0xffffffffu, wm, 2));
    wm = fmaxf(wm, __shfl_xor_sync(0xffffffffu, wm, 1));
    if (lane == 0) red[wid] = wm;
    __syncthreads();
    float m = red[0];
    #pragma unroll
    for (int i = 1; i < 8; i++) m = fmaxf(m, red[i]);

    const float w = __expf(lg - m);
    w_sh[t] = w;
    float ws = w;
    ws += __shfl_xor_sync(0xffffffffu, ws, 16);
    ws += __shfl_xor_sync(0xffffffffu, ws, 8);
    ws += __shfl_xor_sync(0xffffffffu, ws, 4);
    ws += __shfl_xor_sync(0xffffffffu, ws, 2);
    ws += __shfl_xor_sync(0xffffffffu, ws, 1);
    if (lane == 0) red[8 + wid] = ws;
    __syncthreads();            // publishes w_sh AND red[8..15]
    float s_tot = red[8];
    #pragma unroll
    for (int i = 1; i < 8; i++) s_tot += red[8 + i];

    // ---- P3: weighted v accumulate. Thread owns float2 dim d2 = t&31;
    // group g = t>>5 (8 groups) owns rows g, g+8, ... (coalesced). ----
    {
        const int d2 = t & 31;
        const int g  = t >> 5;
        const float2* vb = (const float2*)(v + ((size_t)b * LL + row0) * DD);
        float2 acc = make_float2(0.f, 0.f);
        #pragma unroll 8
        for (int r = g; r < CH; r += 8) {
            float2 vv = vb[(size_t)r * 32 + d2];
            float wr = w_sh[r];
            acc.x += wr * vv.x; acc.y += wr * vv.y;
        }

        // cross-group reduce (reuse psum as float2 scratch)
        float2* redf2 = (float2*)psum;
        redf2[t] = acc;
        __syncthreads();
        if (t < 32) {
            float2 tot = make_float2(0.f, 0.f);
            #pragma unroll
            for (int i = 0; i < 8; i++) {
                float2 x = redf2[i * 32 + t];
                tot.x += x.x; tot.y += x.y;
            }
            ((float2*)(g_partial_acc + ((size_t)b * NSPLIT + c) * DD))[t] = tot;
        }
        if (t == 0) {
            g_partial_m[b * NSPLIT + c] = m;
            g_partial_s[b * NSPLIT + c] = s_tot;
        }
    }
}

// ---------------------------------------------------------------------------
// Diffuse (fused combine): one 256-row tile per block. grid (32, 64),
// 256 threads. launch_bounds caps regs at 32 -> 8 blocks/SM (full occ).
// ---------------------------------------------------------------------------
__global__ void __launch_bounds__(256, 8)
diffuse_kernel(const float* __restrict__ q,
               const float* __restrict__ kd,
               const float* __restrict__ td,
               float* __restrict__ out)
{
    __shared__ float  psum[CH * 17];
    __shared__ float  gate_sh[CH];
    __shared__ float  attn_sh[DD];
    __shared__ float4 q4_sh[16];

    const int b = blockIdx.y;
    const int t = threadIdx.x;
    const int row0 = blockIdx.x * CH;

    // --- combine partials -> attn_sh (threads 0..63; L2-hot) ---
    if (t < DD) {
        float M = -FLT_MAX;
        #pragma unroll
        for (int i = 0; i < NSPLIT; i++)
            M = fmaxf(M, g_partial_m[b * NSPLIT + i]);
        float S = 0.f, num = 0.f;
        #pragma unroll
        for (int i = 0; i < NSPLIT; i++) {
            float e = __expf(g_partial_m[b * NSPLIT + i] - M);
            S   += g_partial_s[b * NSPLIT + i] * e;
            num += g_partial_acc[((size_t)b * NSPLIT + i) * DD + t] * e;
        }
        attn_sh[t] = num / S;
    }
    if (t < 16) q4_sh[t] = ((const float4*)(q + b * DD))[t];
    __syncthreads();

    const float inv_td = 1.0f / *td;
    const int seg  = t & 15;
    const int rsub = t >> 4;
    const float4 qv = q4_sh[seg];
    const float4 av = ((const float4*)attn_sh)[seg];

    // ---- P1: 16 independent coalesced kd loads -> psum ----
    const float4* kd4 = (const float4*)(kd + (size_t)b * LL * DD);
    #pragma unroll
    for (int i = 0; i < 16; i++) {
        const int row = i * 16 + rsub;
        float4 kv = kd4[(size_t)(row0 + row) * 16 + seg];
        psum[row * 17 + seg] =
            kv.x * qv.x + kv.y * qv.y + kv.z * qv.z + kv.w * qv.w;
    }
    __syncthreads();

    // ---- P2: per-thread gate ----
    {
        float s = 0.f;
        #pragma unroll
        for (int j = 0; j < 16; j++) s += psum[t * 17 + j];
        gate_sh[t] = 1.0f / (1.0f + __expf(-s * inv_td));
    }
    __syncthreads();

    // ---- P3: pure streaming store ----
    float4* o4 = (float4*)(out + (size_t)b * LL * DD);
    #pragma unroll
    for (int i = 0; i < 16; i++) {
        const int row = i * 16 + rsub;
        const float g = gate_sh[row];
        o4[(size_t)(row0 + row) * 16 + seg] =
            make_float4(g * av.x, g * av.y, g * av.z, g * av.w);
    }
}

// ---------------------------------------------------------------------------
extern "C" void kernel_launch(void* const* d_in, const int* in_sizes, int n_in,
                              void* d_out, int out_size)
{
    const float* q  = (const float*)d_in[0];
    const float* kc = (const float*)d_in[1];
    const float* kd = (const float*)d_in[2];
    const float* v  = (const float*)d_in[3];
    const float* tc = (const float*)d_in[4];
    const float* td = (const float*)d_in[5];

    float* out_main  = (float*)d_out;                         // [B, L, D]
    float* out_logit = (float*)d_out + (size_t)BB * LL * DD;  // [B, L]

    collect_kernel<<<dim3(NSPLIT, BB), 256>>>(q, kc, v, tc, out_logit);
    diffuse_kernel<<<dim3(LL / CH, BB), 256>>>(q, kd, td, out_main);
}